// round 6
// baseline (speedup 1.0000x reference)
#include <cuda_runtime.h>
#include <math.h>

#define T 64
#define THREADS 256
#define PITCH 65   // +1 float pad; scalar LDS only, <=2-way conflicts both phases

// Uncompress packed strict-upper-triangle vector (row-major, j>i) into a full
// symmetric n x n matrix with unit diagonal.
//   idx(i,j) = i*(n-1) - i*(i-1)/2 + (j - i - 1)
//
// Triangular grid: one block per upper-triangle 64x64 tile (bj >= bi).
// Off-diagonal block:
//   phase 0: cp.async comp -> smem (no data registers -> low reg pressure,
//            8 blocks/SM = 100% occ; MLP funded by the async queue, not RF)
//   phase 1: float4-gather smem rows   -> STG.128 upper tile
//   phase 2: float4-gather smem columns-> STG.128 mirror tile
__global__ void __launch_bounds__(THREADS, 8)
uncompress_sym_kernel(const float* __restrict__ comp,
                      float* __restrict__ out,
                      int n, int nb) {
    __shared__ float s[T * PITCH];

    // Linear block id -> (bi, bj) in the upper triangle (row-major, incl diag).
    // start(bi) = bi*(2*nb - bi + 1)/2
    const int t = blockIdx.x;
    const float ff = (float)nb + 0.5f;
    int bi = (int)(ff - sqrtf(fmaxf(ff * ff - 2.0f * (float)t, 0.0f)));
    if (bi > nb - 1) bi = nb - 1;
    if (bi < 0) bi = 0;
    while (bi + 1 <= nb - 1 && ((bi + 1) * (2 * nb - bi)) / 2 <= t) bi++;
    while (bi > 0 && (bi * (2 * nb - bi + 1)) / 2 > t) bi--;
    const int bj = bi + (t - (bi * (2 * nb - bi + 1)) / 2);

    const int i0 = bi * T;
    const int j0 = bj * T;
    const int tid = threadIdx.x;

    if (bi != bj) {
        // Phase 0: async copy tile into smem, coalesced (contiguous in j).
        const unsigned sbase = (unsigned)__cvta_generic_to_shared(s);
        #pragma unroll
        for (int it = 0; it < (T * T) / THREADS; it++) {
            const int idx = it * THREADS + tid;
            const int r = idx >> 6;
            const int c = idx & 63;
            const int i = i0 + r;
            const int j = j0 + c;
            const int ci = i * (n - 1) - ((i * (i - 1)) >> 1) + (j - i - 1);
            asm volatile("cp.async.ca.shared.global [%0], [%1], 4;\n"
                         :: "r"(sbase + (unsigned)((r * PITCH + c) * 4)),
                            "l"(comp + ci));
        }
        asm volatile("cp.async.commit_group;\n");
        asm volatile("cp.async.wait_group 0;\n" ::: "memory");
        __syncthreads();

        // Phase 1: upper tile, row-major gather, STG.128 (j0+c4 mult of 4).
        #pragma unroll
        for (int it = 0; it < (T * T) / (THREADS * 4); it++) {
            const int idx = it * THREADS + tid;
            const int r  = idx >> 4;            // 0..63
            const int c4 = (idx & 15) << 2;     // 0,4,...,60
            float4 v;
            v.x = s[r * PITCH + c4 + 0];
            v.y = s[r * PITCH + c4 + 1];
            v.z = s[r * PITCH + c4 + 2];
            v.w = s[r * PITCH + c4 + 3];
            *(float4*)&out[(size_t)(i0 + r) * n + (j0 + c4)] = v;
        }
        // Phase 2: mirror tile out[j][i] = tile^T, column gather, STG.128.
        #pragma unroll
        for (int it = 0; it < (T * T) / (THREADS * 4); it++) {
            const int idx = it * THREADS + tid;
            const int r  = idx >> 4;
            const int c4 = (idx & 15) << 2;
            float4 v;
            v.x = s[(c4 + 0) * PITCH + r];
            v.y = s[(c4 + 1) * PITCH + r];
            v.z = s[(c4 + 2) * PITCH + r];
            v.w = s[(c4 + 3) * PITCH + r];
            *(float4*)&out[(size_t)(j0 + r) * n + (i0 + c4)] = v;
        }
    } else {
        // Diagonal tile (128 of 8256 blocks): load strict upper, mirror in smem.
        #pragma unroll
        for (int it = 0; it < (T * T) / THREADS; it++) {
            const int idx = it * THREADS + tid;
            const int r = idx >> 6;
            const int c = idx & 63;
            const int i = i0 + r;
            const int j = j0 + c;
            float v = 0.0f;
            if (j > i) {
                const int ci = i * (n - 1) - ((i * (i - 1)) >> 1) + (j - i - 1);
                v = comp[ci];
            }
            s[r * PITCH + c] = v;
        }
        __syncthreads();
        #pragma unroll
        for (int it = 0; it < (T * T) / THREADS; it++) {
            const int idx = it * THREADS + tid;
            const int r = idx >> 6;
            const int c = idx & 63;
            float v;
            if (c > r)       v = s[r * PITCH + c];
            else if (c == r) v = 1.0f;
            else             v = s[c * PITCH + r];
            out[(size_t)(i0 + r) * n + (j0 + c)] = v;
        }
    }
}

extern "C" void kernel_launch(void* const* d_in, const int* in_sizes, int n_in,
                              void* d_out, int out_size) {
    const float* comp = (const float*)d_in[0];
    float* out = (float*)d_out;

    // n = round(sqrt(2m)) + 1 — MUST be double: sqrt(2*33550336) = 8191.49998,
    // which rounds to exactly 8191.5 in fp32 and would give n=8193 (OOB).
    const long long m = (long long)in_sizes[0];
    const int n = (int)llround(sqrt(2.0 * (double)m)) + 1;  // 8192
    const int nb = n / T;                                   // 128

    const int nblocks = nb * (nb + 1) / 2;                  // 8256
    uncompress_sym_kernel<<<nblocks, THREADS>>>(comp, out, n, nb);
}